// round 5
// baseline (speedup 1.0000x reference)
#include <cuda_runtime.h>
#include <stdint.h>

// Problem constants
#define VS 64
#define DEPTH_HW 256
#define IMG_H 1024
#define IMG_W 1280
#define BATCH 8
#define OUT_PER_B (VS * VS * VS)           // 262144 voxels per batch
#define N_OUT (BATCH * OUT_PER_B)          // 2097152 floats out
#define NWORD (OUT_PER_B / 4)              // 65536 words per replica
#define R 16                               // replicas (break hot-address atomic serialization)

// Bit layout: word w covers voxels lin = 4w..4w+3 (same ix,iy, one z-group)
// ACROSS ALL 8 BATCHES: bit = (lin&3)*8 + b. This makes cross-batch
// duplicates (same ray, close depths -> same voxel) share an address so a
// thread can merge them into one atomic.
// 16 replicas x 256KB = 4MB. Zeroed at module load; expand restores zero
// every call so each kernel_launch / graph replay starts clean.
__device__ unsigned g_bits[R][NWORD];

// Scatter: one thread per non-padded pixel; warp covers a 4(y) x 8(x) tile
// so each per-batch depth load is one 128B line. Per thread: compute the 8
// (word, maskbit) pairs, merge pairs that hit the same word, then REDG.OR
// the survivors into this warp's replica.
__global__ void __launch_bounds__(256)
vox_scatter_kernel(const float* __restrict__ depth,   // [8,256,256]
                   const float* __restrict__ ray)     // [1280*1024, 3]
{
    const int lane = threadIdx.x & 31;
    const int wid  = threadIdx.x >> 5;            // 0..7
    const int bx   = blockIdx.x & 127;            // 128 x-tiles of width 8
    const int by   = blockIdx.x >> 7;             // 32  y-tiles of height 32

    const int y  = by * 32 + wid * 4 + (lane & 3);   // 0..1023
    const int xr = bx * 8 + (lane >> 2);             // 0..1023 (non-padded x)

    unsigned* __restrict__ bits = g_bits[((blockIdx.x << 3) + wid) & (R - 1)];

    // ray index: column-major flatten idx = x*1024 + y, x = xr + 128
    const int ridx = ((xr + 128) << 10) + y;
    const float rx = __ldg(&ray[3 * ridx + 0]);
    const float ry = __ldg(&ray[3 * ridx + 1]);
    const float rz = __ldg(&ray[3 * ridx + 2]);

    const float scale = 64.0f / 3.0f;
    const int doff = ((y >> 2) << 8) + (xr >> 2);    // depth[b, y/4, xr/4]

    int      wz[BATCH];     // word index (or unique sentinel if out of range)
    unsigned m[BATCH];      // accumulated bit mask for that word
    bool     keep[BATCH];   // this slot still issues an atomic

#pragma unroll
    for (int b = 0; b < BATCH; b++) {
        const float d = __ldg(&depth[b * (DEPTH_HW * DEPTH_HW) + doff]);

        // Replicate reference f32 op sequence exactly: mul, add, mul,
        // round-half-even. _rn intrinsics forbid FFMA contraction.
        const float px = __fmul_rn(rx, d);
        const float py = __fmul_rn(ry, d);
        const float pz = __fmul_rn(rz, d);

        const int ix = __float2int_rn(__fmul_rn(__fadd_rn(px, 1.5f), scale));
        const int iy = __float2int_rn(__fmul_rn(__fadd_rn(py, 1.5f), scale));
        const int iz = __float2int_rn(__fmul_rn(pz, scale));

        const bool good = ((unsigned)ix < 64u) & ((unsigned)iy < 64u) &
                          ((unsigned)iz < 64u);
        const int lin = (((ix << 6) + iy) << 6) + iz;

        const int      wd = good ? (lin >> 2) : (0x40000000 + b);  // sentinel unique per b
        const unsigned mk = 1u << (((lin & 3) << 3) + b);

        // Merge into the first earlier kept slot with the same word.
        bool merged = false;
#pragma unroll
        for (int j = 0; j < b; j++) {
            if (!merged && wd == wz[j] && keep[j]) { m[j] |= mk; merged = true; }
        }
        wz[b]   = wd;
        m[b]    = mk;
        keep[b] = good && !merged;
    }

#pragma unroll
    for (int b = 0; b < BATCH; b++) {
        if (keep[b]) atomicOr(&bits[wz[b]], m[b]);
    }

    // Padded columns all have depth==0 -> voxel (32,32,0) for every batch:
    // lin = 133120 -> word 33280, z-group offset 0, all 8 batch bits.
    if (blockIdx.x == 0 && threadIdx.x == 0) {
        atomicOr(&g_bits[0][33280], 0xFFu);
    }
}

// Expand: one thread per word. OR the 16 replicas, emit one coalesced float4
// per batch (the word's 4 voxels are exactly one output float4), then zero
// the replica words (each thread owns its word exclusively; loads precede
// stores in program order). Writes every output element, so no zero pass.
__global__ void __launch_bounds__(256)
vox_expand_kernel(float4* __restrict__ out)
{
    const int w = blockIdx.x * 256 + threadIdx.x;   // 0 .. NWORD-1

    unsigned v = 0;
#pragma unroll
    for (int r = 0; r < R; r++) v |= g_bits[r][w];

#pragma unroll
    for (int b = 0; b < BATCH; b++) {
        float4 o;
        o.x = ((v >> (0 * 8 + b)) & 1u) ? 1.0f : 0.0f;
        o.y = ((v >> (1 * 8 + b)) & 1u) ? 1.0f : 0.0f;
        o.z = ((v >> (2 * 8 + b)) & 1u) ? 1.0f : 0.0f;
        o.w = ((v >> (3 * 8 + b)) & 1u) ? 1.0f : 0.0f;
        out[b * NWORD + w] = o;
    }

#pragma unroll
    for (int r = 0; r < R; r++) g_bits[r][w] = 0u;
}

extern "C" void kernel_launch(void* const* d_in, const int* in_sizes, int n_in,
                              void* d_out, int out_size)
{
    const float* depth = (const float*)d_in[0];
    const float* ray   = (const float*)d_in[1];
    // Defensive: identify by element count (depth = 524288, ray = 3932160)
    if (n_in >= 2 && in_sizes[0] == IMG_W * IMG_H * 3) {
        ray   = (const float*)d_in[0];
        depth = (const float*)d_in[1];
    }
    float* out = (float*)d_out;

    vox_scatter_kernel<<<4096, 256>>>(depth, ray);
    vox_expand_kernel<<<NWORD / 256, 256>>>((float4*)out);
}